// round 16
// baseline (speedup 1.0000x reference)
#include <cuda_runtime.h>
#include <cuda_fp16.h>
#include <cstdint>

#define Bb 2
#define Ss 2048
#define Dd 2048
#define Hh 16
#define HD 128
#define Mtot (Bb*Ss)

// fp16 pair-layout scratch (half2 stored as uint32_t).
// Row of K halfs -> K/2 half2, grouped in 16-k blocks (8 half2); within a
// block, half2 j (local 0..7) at position pos(j) = (j&3)*2 + (j>>2). A thread
// (lc) reads positions {2lc,2lc+1} as one LDS.64 = m16n8k16 klo/khi pair.
// XPh/APh: [Mtot][1024]
// WPh:     [128 kb][2048 n][8]
// QPh/KPh: [bh=32][s=2048][64]
// VPh:     [bh=32][128 d][1024]  (pairs along s)
__device__ uint32_t g_XPh[(size_t)Mtot * 1024];
__device__ uint32_t g_WPq[(size_t)128 * 2048 * 8];
__device__ uint32_t g_WPk[(size_t)128 * 2048 * 8];
__device__ uint32_t g_WPv[(size_t)128 * 2048 * 8];
__device__ uint32_t g_WPd[(size_t)128 * 2048 * 8];
__device__ uint32_t g_QPh[(size_t)Bb * Hh * Ss * 64];
__device__ uint32_t g_KPh[(size_t)Bb * Hh * Ss * 64];
__device__ uint32_t g_VPh[(size_t)Bb * Hh * 128 * 1024];
__device__ uint32_t g_APh[(size_t)Mtot * 1024];

__device__ __forceinline__ uint32_t f2h2(float a, float b) {
    __half2 h = __floats2half2_rn(a, b);
    return *(uint32_t*)&h;
}

__device__ __forceinline__ void mma16(float* c, const uint32_t* a, const uint32_t* b) {
    asm volatile(
        "mma.sync.aligned.m16n8k16.row.col.f32.f16.f16.f32 "
        "{%0,%1,%2,%3}, {%4,%5,%6,%7}, {%8,%9}, {%0,%1,%2,%3};"
        : "+f"(c[0]), "+f"(c[1]), "+f"(c[2]), "+f"(c[3])
        : "r"(a[0]), "r"(a[1]), "r"(a[2]), "r"(a[3]), "r"(b[0]), "r"(b[1]));
}
__device__ __forceinline__ void cpa16(void* dst, const void* src) {
    uint32_t d = (uint32_t)__cvta_generic_to_shared(dst);
    asm volatile("cp.async.cg.shared.global [%0], [%1], 16;" :: "r"(d), "l"(src));
}
#define CP_COMMIT asm volatile("cp.async.commit_group;")
#define CP_WAIT1  asm volatile("cp.async.wait_group 1;")
#define CP_WAIT0  asm volatile("cp.async.wait_group 0;")

__device__ __forceinline__ int ppos(int jl) { return (jl & 3) * 2 + ((jl >> 2) & 1); }

// ---------------------------------------------------------------------------
// Prep kernels (R12, verified)
// ---------------------------------------------------------------------------
__global__ void xprep_h(const float* __restrict__ X, uint32_t* __restrict__ XP) {
    __shared__ float s[2048];
    const int m = blockIdx.x;
    const int tid = threadIdx.x;
    const float* src = X + (size_t)m * 2048;
#pragma unroll
    for (int i = 0; i < 2; i++) {
        int f = i * 256 + tid;
        *(float4*)(s + f * 4) = *(const float4*)(src + f * 4);
    }
    __syncthreads();
    const int b = tid >> 1;
    const int w0 = (tid & 1) * 4;
    uint32_t o[4];
#pragma unroll
    for (int q = 0; q < 4; q++) {
        int w = w0 + q;
        int j = b * 8 + (w >> 1) + (w & 1) * 4;
        o[q] = f2h2(s[2 * j], s[2 * j + 1]);
    }
    *(uint4*)(XP + (size_t)m * 1024 + tid * 4) = make_uint4(o[0], o[1], o[2], o[3]);
}

__global__ void wprep4_h(const float* __restrict__ W0, const float* __restrict__ W1,
                         const float* __restrict__ W2, const float* __restrict__ W3,
                         uint32_t* __restrict__ P0, uint32_t* __restrict__ P1,
                         uint32_t* __restrict__ P2, uint32_t* __restrict__ P3) {
    __shared__ float s[16 * 260];
    const int n0 = blockIdx.x * 256;
    const int kb = blockIdx.y;
    const int z  = blockIdx.z;
    const int tid = threadIdx.x;
    const float* W = (z == 0) ? W0 : (z == 1) ? W1 : (z == 2) ? W2 : W3;
    uint32_t* WP   = (z == 0) ? P0 : (z == 1) ? P1 : (z == 2) ? P2 : P3;
#pragma unroll
    for (int i = 0; i < 4; i++) {
        int f = i * 256 + tid;
        int r = f >> 6, c4 = (f & 63) * 4;
        float4 v = *(const float4*)(W + (size_t)(kb * 16 + r) * 2048 + n0 + c4);
        *(float4*)(s + r * 260 + c4) = v;
    }
    __syncthreads();
    const int n = tid;
    uint32_t o[8];
#pragma unroll
    for (int w = 0; w < 8; w++) {
        int j = (w >> 1) + (w & 1) * 4;
        o[w] = f2h2(s[(2 * j) * 260 + n], s[(2 * j + 1) * 260 + n]);
    }
    uint32_t* dst = WP + ((size_t)kb * 2048 + n0 + n) * 8;
    *(uint4*)(dst)     = make_uint4(o[0], o[1], o[2], o[3]);
    *(uint4*)(dst + 4) = make_uint4(o[4], o[5], o[6], o[7]);
}

// ---------------------------------------------------------------------------
// PERSISTENT fp16 tensor-core GEMM, 3-stage BK32 ring, ONE sync per stage.
// Grid = 296 CTAs. Tile map: bx = t&15, by = (t>>4)&31, z = t>>9.
// modes: 0 plain fp32 C; 1 Q->QPh (qscale); 2 K->k_out+KPh; 3 V->v_out+VPh
// ---------------------------------------------------------------------------
#define HASTR 24
#define HABUF (128 * HASTR)
#define HBBUF (2 * 128 * 8)
#define HGBUF (HABUF + HBBUF)

__global__ __launch_bounds__(256, 2)
void gemm_h(const uint32_t* __restrict__ Ap,
            const uint32_t* __restrict__ Wa, const uint32_t* __restrict__ Wb,
            const uint32_t* __restrict__ Wc,
            const float* __restrict__ ba, const float* __restrict__ bb,
            const float* __restrict__ bc,
            float* __restrict__ ra, float* __restrict__ rb, float* __restrict__ rc,
            uint32_t* __restrict__ pa, uint32_t* __restrict__ pb, uint32_t* __restrict__ pc,
            int modebase, int ntiles)
{
    extern __shared__ uint32_t smu[];

    const int tid  = threadIdx.x;
    const int lane = tid & 31;
    const int wid  = tid >> 5;
    const int mb   = (wid >> 1) * 32;
    const int nb   = (wid & 1) * 64;
    const int lr   = lane >> 2;
    const int lc   = lane & 3;

    for (int tile = blockIdx.x; tile < ntiles; tile += gridDim.x) {
        const int bx = tile & 15;
        const int by = (tile >> 4) & 31;
        const int z  = tile >> 9;
        const uint32_t* WP = (z == 0) ? Wa : (z == 1) ? Wb : Wc;
        const float* bias  = (z == 0) ? ba : (z == 1) ? bb : bc;
        float* Craw        = (z == 0) ? ra : (z == 1) ? rb : rc;
        uint32_t* Cpair    = (z == 0) ? pa : (z == 1) ? pb : pc;
        const int mode = modebase ? (1 + z) : 0;

        float acc[2][8][4];
#pragma unroll
        for (int f = 0; f < 2; f++)
#pragma unroll
            for (int g = 0; g < 8; g++)
#pragma unroll
                for (int t = 0; t < 4; t++) acc[f][g][t] = 0.f;

        auto issue = [&](int kt, int buf) {
            uint32_t* As = smu + buf * HGBUF;
            uint32_t* Bs = As + HABUF;
#pragma unroll
            for (int j = 0; j < 2; j++) {
                int idx = j * 256 + tid;
                int m = idx >> 2, ch = idx & 3;
                cpa16(As + m * HASTR + ch * 4,
                      Ap + (size_t)(by * 128 + m) * 1024 + kt * 16 + ch * 4);
            }
#pragma unroll
            for (int j = 0; j < 2; j++) {
                int idx = j * 256 + tid;
                int kb = idx >> 8, r = idx & 255, n = r >> 1, ch = r & 1;
                cpa16(Bs + kb * 1024 + n * 8 + ch * 4,
                      WP + ((size_t)(kt * 2 + kb) * 2048 + bx * 128 + n) * 8 + ch * 4);
            }
        };

        issue(0, 0); CP_COMMIT;
        issue(1, 1); CP_COMMIT;

        int bcur = 0;                      // kt % 3
        for (int kt = 0; kt < 64; kt++) {
            CP_WAIT1;                      // stage kt's group complete
            __syncthreads();               // compute kt-1 done -> safe to refill
            if (kt + 2 < 64) {
                int bnext = bcur + 2; if (bnext >= 3) bnext -= 3;
                issue(kt + 2, bnext);
                CP_COMMIT;
            }

            const uint32_t* As = smu + bcur * HGBUF;
            const uint32_t* Bs = As + HABUF;

#pragma unroll
            for (int kb = 0; kb < 2; kb++) {
                const int ao = kb * 8 + 2 * lc;
                uint2 x0 = *(const uint2*)(As + (mb + lr) * HASTR + ao);
                uint2 x1 = *(const uint2*)(As + (mb + lr + 8) * HASTR + ao);
                uint2 x2 = *(const uint2*)(As + (mb + 16 + lr) * HASTR + ao);
                uint2 x3 = *(const uint2*)(As + (mb + 24 + lr) * HASTR + ao);
                uint32_t a0[4] = {x0.x, x1.x, x0.y, x1.y};
                uint32_t a1[4] = {x2.x, x3.x, x2.y, x3.y};
                const uint32_t* bp = Bs + kb * 1024 + (nb + lr) * 8 + 2 * lc;
#pragma unroll
                for (int g = 0; g < 8; g++) {
                    uint2 bv = *(const uint2*)(bp + g * 64);
                    uint32_t b[2] = {bv.x, bv.y};
                    mma16(acc[0][g], a0, b);
                    mma16(acc[1][g], a1, b);
                }
            }
            if (++bcur == 3) bcur = 0;
        }

        const float qscale = 0.08838834764831845f;
#pragma unroll
        for (int f = 0; f < 2; f++) {
#pragma unroll
            for (int g = 0; g < 8; g++) {
#pragma unroll
                for (int ii = 0; ii < 2; ii++) {
                    int row = by * 128 + mb + f * 16 + lr + 8 * ii;
                    int col0 = bx * 128 + nb + g * 8 + lc * 2;
                    float v0 = acc[f][g][ii * 2 + 0] + bias[col0];
                    float v1 = acc[f][g][ii * 2 + 1] + bias[col0 + 1];
                    if (mode == 0) {
                        float* p = Craw + (size_t)row * Dd + col0;
                        p[0] = v0; p[1] = v1;
                    } else {
                        int b_ = row >> 11, s_ = row & 2047;
                        int h_ = col0 >> 7, d_ = col0 & 127;
                        size_t bh = (size_t)(b_ * Hh + h_);
                        if (mode >= 2) {
                            float* p = Craw + (bh * Ss + s_) * HD + d_;
                            p[0] = v0; p[1] = v1;
                        }
                        if (mode == 3) {
                            float u0 = __shfl_xor_sync(0xffffffffu, v0, 4);
                            float u1 = __shfl_xor_sync(0xffffffffu, v1, 4);
                            if (!(lr & 1)) {
                                int js = s_ >> 1;
                                size_t slot = (size_t)(js >> 3) * 8 + ppos(js & 7);
                                Cpair[(bh * 128 + d_) * 1024 + slot]     = f2h2(v0, u0);
                                Cpair[(bh * 128 + d_ + 1) * 1024 + slot] = f2h2(v1, u1);
                            }
                        } else {
                            float s0 = (mode == 1) ? v0 * qscale : v0;
                            float s1 = (mode == 1) ? v1 * qscale : v1;
                            int j = d_ >> 1;
                            Cpair[(bh * Ss + s_) * 64 + (j >> 3) * 8 + ppos(j & 7)] = f2h2(s0, s1);
                        }
                    }
                }
            }
        }
        __syncthreads();   // protect ring buffers before next tile's prologue
    }
}

// ---------------------------------------------------------------------------
// fp16 flash attention (R14, verified at 142.2us): 128-thread CTAs,
// Q-tile 64 (4 warps x 16 rows), 2 CTAs/SM, KV tiles 64 double-buffered.
// ---------------------------------------------------------------------------
#define HQS 72
#define HKS 72
#define HVS 40
#define ASQ (64 * HQS)
#define ASK (64 * HKS)
#define ASV (128 * HVS)

__global__ __launch_bounds__(128, 2)
void attn_h(const uint32_t* __restrict__ QP, const uint32_t* __restrict__ KP,
            const uint32_t* __restrict__ VP, uint32_t* __restrict__ AP)
{
    extern __shared__ uint32_t smu[];
    uint32_t* sQ = smu;
    uint32_t* sK = sQ + ASQ;
    uint32_t* sV = sK + 2 * ASK;

    const int qt  = (gridDim.x - 1) - blockIdx.x;
    const int bh  = blockIdx.y;
    const int tid = threadIdx.x;
    const int lane = tid & 31;
    const int wid  = tid >> 5;
    const int lr   = lane >> 2;
    const int lc   = lane & 3;
    const int m_off = wid * 16;

    const uint32_t* Qg = QP + ((size_t)bh * Ss + (size_t)qt * 64) * 64;
    const uint32_t* Kg = KP + (size_t)bh * Ss * 64;
    const uint32_t* Vg = VP + (size_t)bh * 128 * 1024;

#pragma unroll
    for (int i = 0; i < 8; i++) {
        int idx = i * 128 + tid;
        int row = idx >> 4, ch = idx & 15;
        cpa16(sQ + row * HQS + ch * 4, Qg + (size_t)row * 64 + ch * 4);
    }
    CP_COMMIT;
#pragma unroll
    for (int i = 0; i < 8; i++) {
        int idx = i * 128 + tid;
        int row = idx >> 4, ch = idx & 15;
        cpa16(sK + row * HKS + ch * 4, Kg + (size_t)row * 64 + ch * 4);
    }
#pragma unroll
    for (int i = 0; i < 8; i++) {
        int idx = i * 128 + tid;
        int d = idx >> 3, ch = idx & 7;
        cpa16(sV + d * HVS + ch * 4, Vg + (size_t)d * 1024 + ch * 4);
    }
    CP_COMMIT;

    CP_WAIT1;
    __syncthreads();
    uint32_t qf[8][4];
#pragma unroll
    for (int kb = 0; kb < 8; kb++) {
        uint2 q0 = *(const uint2*)(sQ + (m_off + lr) * HQS + kb * 8 + 2 * lc);
        uint2 q1 = *(const uint2*)(sQ + (m_off + lr + 8) * HQS + kb * 8 + 2 * lc);
        qf[kb][0] = q0.x; qf[kb][1] = q1.x; qf[kb][2] = q0.y; qf[kb][3] = q1.y;
    }

    float o[16][4];
#pragma unroll
    for (int n = 0; n < 16; n++)
#pragma unroll
        for (int j = 0; j < 4; j++) o[n][j] = 0.f;
    float m0 = -1e30f, m1 = -1e30f, l0 = 0.f, l1 = 0.f;

    const int tmax = qt;

    for (int t = 0; t <= tmax; t++) {
        const int buf = t & 1;
        if (t < tmax) {
            const int nb2 = (t + 1) & 1;
            uint32_t* dK = sK + nb2 * ASK;
            uint32_t* dV = sV + nb2 * ASV;
            const uint32_t* gK = Kg + (size_t)(t + 1) * 64 * 64;
            const uint32_t* gV = Vg + (size_t)(t + 1) * 32;
#pragma unroll
            for (int i = 0; i < 8; i++) {
                int idx = i * 128 + tid;
                int row = idx >> 4, ch = idx & 15;
                cpa16(dK + row * HKS + ch * 4, gK + (size_t)row * 64 + ch * 4);
            }
#pragma unroll
            for (int i = 0; i < 8; i++) {
                int idx = i * 128 + tid;
                int d = idx >> 3, ch = idx & 7;
                cpa16(dV + d * HVS + ch * 4, gV + (size_t)d * 1024 + ch * 4);
            }
            CP_COMMIT;
            CP_WAIT1;
        } else {
            CP_WAIT0;
        }
        __syncthreads();

        {
            const uint32_t* sKb = sK + buf * ASK;
            const uint32_t* sVb = sV + buf * ASV;

            float c[8][4];
#pragma unroll
            for (int n = 0; n < 8; n++)
#pragma unroll
                for (int j = 0; j < 4; j++) c[n][j] = 0.f;

#pragma unroll
            for (int kb = 0; kb < 8; kb++) {
                const uint32_t* kp = sKb + lr * HKS + kb * 8 + 2 * lc;
#pragma unroll
                for (int nf = 0; nf < 8; nf++) {
                    uint2 kv = *(const uint2*)(kp + nf * 8 * HKS);
                    uint32_t b[2] = {kv.x, kv.y};
                    mma16(c[nf], qf[kb], b);
                }
            }

            if (t * 64 + 63 > qt * 64 + m_off) {
#pragma unroll
                for (int nf = 0; nf < 8; nf++) {
#pragma unroll
                    for (int j = 0; j < 4; j++) {
                        int col = t * 64 + nf * 8 + 2 * lc + (j & 1);
                        int row = qt * 64 + m_off + lr + 8 * (j >> 1);
                        if (col > row) c[nf][j] = -1e30f;
                    }
                }
            }

            float mt0 = -1e30f, mt1 = -1e30f;
#pragma unroll
            for (int nf = 0; nf < 8; nf++) {
                mt0 = fmaxf(mt0, fmaxf(c[nf][0], c[nf][1]));
                mt1 = fmaxf(mt1, fmaxf(c[nf][2], c[nf][3]));
            }
#pragma unroll
            for (int d = 1; d <= 2; d <<= 1) {
                mt0 = fmaxf(mt0, __shfl_xor_sync(0xffffffffu, mt0, d));
                mt1 = fmaxf(mt1, __shfl_xor_sync(0xffffffffu, mt1, d));
            }
            float nm0 = fmaxf(m0, mt0), nm1 = fmaxf(m1, mt1);
            float corr0 = __expf(m0 - nm0), corr1 = __expf(m1 - nm1);
            m0 = nm0; m1 = nm1;

            float s0 = 0.f, s1 = 0.f;
#pragma unroll
            for (int nf = 0; nf < 8; nf++) {
                c[nf][0] = __expf(c[nf][0] - nm0); s0 += c[nf][0];
                c[nf][1] = __expf(c[nf][1] - nm0); s0 += c[nf][1];
                c[nf][2] = __expf(c[nf][2] - nm1); s1 += c[nf][2];
                c[nf][3] = __expf(c[nf][3] - nm1); s1 += c[nf][3];
            }
#pragma unroll
            for (int d = 1; d <= 2; d <<= 1) {
                s0 += __shfl_xor_sync(0xffffffffu, s0, d);
                s1 += __shfl_xor_sync(0xffffffffu, s1, d);
            }
            l0 = l0 * corr0 + s0;
            l1 = l1 * corr1 + s1;

            if (__any_sync(0xffffffffu, (corr0 != 1.f) || (corr1 != 1.f))) {
#pragma unroll
                for (int n = 0; n < 16; n++) {
                    o[n][0] *= corr0; o[n][1] *= corr0;
                    o[n][2] *= corr1; o[n][3] *= corr1;
                }
            }

#pragma unroll
            for (int kp2 = 0; kp2 < 4; kp2++) {
                uint32_t a[4];
                a[0] = f2h2(c[2 * kp2][0],     c[2 * kp2][1]);
                a[1] = f2h2(c[2 * kp2][2],     c[2 * kp2][3]);
                a[2] = f2h2(c[2 * kp2 + 1][0], c[2 * kp2 + 1][1]);
                a[3] = f2h2(c[2 * kp2 + 1][2], c[2 * kp2 + 1][3]);
                const uint32_t* vp = sVb + lr * HVS + kp2 * 8 + 2 * lc;
#pragma unroll
                for (int nf = 0; nf < 16; nf++) {
                    uint2 vv = *(const uint2*)(vp + nf * 8 * HVS);
                    uint32_t b[2] = {vv.x, vv.y};
                    mma16(o[nf], a, b);
                }
            }
        }
        __syncthreads();
    }

    const float inv0 = 1.0f / l0;
    const float inv1 = 1.0f / l1;
    const int b = bh / Hh;
    const int h = bh % Hh;
    const size_t mrow0 = (size_t)b * 2048 + qt * 64 + m_off + lr;
    const size_t mrow1 = mrow0 + 8;
#pragma unroll
    for (int nf = 0; nf < 16; nf++) {
        int j = h * 64 + nf * 4 + lc;
        size_t slot = (size_t)(j >> 3) * 8 + ppos(j & 7);
        AP[mrow0 * 1024 + slot] = f2h2(o[nf][0] * inv0, o[nf][1] * inv0);
        AP[mrow1 * 1024 + slot] = f2h2(o[nf][2] * inv1, o[nf][3] * inv1);
    }
}

// ---------------------------------------------------------------------------

extern "C" void kernel_launch(void* const* d_in, const int* in_sizes, int n_in,
                              void* d_out, int out_size)
{
    const float* x  = (const float*)d_in[0];
    const float* Wq = (const float*)d_in[1];
    const float* bq = (const float*)d_in[2];
    const float* Wk = (const float*)d_in[3];
    const float* bk = (const float*)d_in[4];
    const float* Wv = (const float*)d_in[5];
    const float* bv = (const float*)d_in[6];
    const float* Wd = (const float*)d_in[7];
    const float* bd = (const float*)d_in[8];

    float* out = (float*)d_out;
    float* a_out = out;
    float* k_out = out + (size_t)Bb * Ss * Dd;
    float* v_out = k_out + (size_t)Bb * Ss * Dd;

    uint32_t *xp, *wpq, *wpk, *wpv, *wpd, *qp, *kp, *vp, *ap;
    cudaGetSymbolAddress((void**)&xp,  g_XPh);
    cudaGetSymbolAddress((void**)&wpq, g_WPq);
    cudaGetSymbolAddress((void**)&wpk, g_WPk);
    cudaGetSymbolAddress((void**)&wpv, g_WPv);
    cudaGetSymbolAddress((void**)&wpd, g_WPd);
    cudaGetSymbolAddress((void**)&qp,  g_QPh);
    cudaGetSymbolAddress((void**)&kp,  g_KPh);
    cudaGetSymbolAddress((void**)&vp,  g_VPh);
    cudaGetSymbolAddress((void**)&ap,  g_APh);

    xprep_h<<<Mtot, 256>>>(x, xp);
    wprep4_h<<<dim3(8, 128, 4), 256>>>(Wq, Wk, Wv, Wd, wpq, wpk, wpv, wpd);

    size_t gsm = 3 * (size_t)HGBUF * sizeof(uint32_t);
    cudaFuncSetAttribute(gemm_h, cudaFuncAttributeMaxDynamicSharedMemorySize, (int)gsm);

    const int PERSIST = 296;   // 2 CTAs/SM x 148 SMs

    // fused QKV (persistent): tiles 0..1535, z = tile>>9; modes 1,2,3
    gemm_h<<<PERSIST, 256, gsm>>>(
        xp, wpq, wpk, wpv, bq, bk, bv,
        nullptr, k_out, v_out, qp, kp, vp, 1, 1536);

    size_t asm_ = (size_t)(ASQ + 2 * ASK + 2 * ASV) * sizeof(uint32_t);
    cudaFuncSetAttribute(attn_h, cudaFuncAttributeMaxDynamicSharedMemorySize, (int)asm_);
    attn_h<<<dim3(Ss / 64, Bb * Hh), 128, asm_>>>(qp, kp, vp, ap);

    // final projection (persistent): tiles 0..511, mode 0
    gemm_h<<<PERSIST, 256, gsm>>>(
        ap, wpd, wpd, wpd, bd, bd, bd,
        a_out, a_out, a_out, nullptr, nullptr, nullptr, 0, 512);
}

// round 17
// speedup vs baseline: 1.0050x; 1.0050x over previous
#include <cuda_runtime.h>
#include <cuda_fp16.h>
#include <cstdint>

#define Bb 2
#define Ss 2048
#define Dd 2048
#define Hh 16
#define HD 128
#define Mtot (Bb*Ss)

// fp16 pair-layout scratch (half2 stored as uint32_t).
// Row of K halfs -> K/2 half2, grouped in 16-k blocks (8 half2); within a
// block, half2 j (local 0..7) at position pos(j) = (j&3)*2 + (j>>2). A thread
// (lc) reads positions {2lc,2lc+1} as one LDS.64 = m16n8k16 klo/khi pair.
// XPh/APh: [Mtot][1024]
// WPh:     [128 kb][2048 n][8]
// QPh/KPh: [bh=32][s=2048][64]
// VPh:     [bh=32][128 d][1024]  (pairs along s)
__device__ uint32_t g_XPh[(size_t)Mtot * 1024];
__device__ uint32_t g_WPq[(size_t)128 * 2048 * 8];
__device__ uint32_t g_WPk[(size_t)128 * 2048 * 8];
__device__ uint32_t g_WPv[(size_t)128 * 2048 * 8];
__device__ uint32_t g_WPd[(size_t)128 * 2048 * 8];
__device__ uint32_t g_QPh[(size_t)Bb * Hh * Ss * 64];
__device__ uint32_t g_KPh[(size_t)Bb * Hh * Ss * 64];
__device__ uint32_t g_VPh[(size_t)Bb * Hh * 128 * 1024];
__device__ uint32_t g_APh[(size_t)Mtot * 1024];

__device__ __forceinline__ uint32_t f2h2(float a, float b) {
    __half2 h = __floats2half2_rn(a, b);
    return *(uint32_t*)&h;
}

__device__ __forceinline__ void mma16(float* c, const uint32_t* a, const uint32_t* b) {
    asm volatile(
        "mma.sync.aligned.m16n8k16.row.col.f32.f16.f16.f32 "
        "{%0,%1,%2,%3}, {%4,%5,%6,%7}, {%8,%9}, {%0,%1,%2,%3};"
        : "+f"(c[0]), "+f"(c[1]), "+f"(c[2]), "+f"(c[3])
        : "r"(a[0]), "r"(a[1]), "r"(a[2]), "r"(a[3]), "r"(b[0]), "r"(b[1]));
}
__device__ __forceinline__ void cpa16(void* dst, const void* src) {
    uint32_t d = (uint32_t)__cvta_generic_to_shared(dst);
    asm volatile("cp.async.cg.shared.global [%0], [%1], 16;" :: "r"(d), "l"(src));
}
#define CP_COMMIT asm volatile("cp.async.commit_group;")
#define CP_WAIT1  asm volatile("cp.async.wait_group 1;")
#define CP_WAIT0  asm volatile("cp.async.wait_group 0;")

__device__ __forceinline__ int ppos(int jl) { return (jl & 3) * 2 + ((jl >> 2) & 1); }

// ---------------------------------------------------------------------------
// Prep kernels (R12, verified)
// ---------------------------------------------------------------------------
__global__ void xprep_h(const float* __restrict__ X, uint32_t* __restrict__ XP) {
    __shared__ float s[2048];
    const int m = blockIdx.x;
    const int tid = threadIdx.x;
    const float* src = X + (size_t)m * 2048;
#pragma unroll
    for (int i = 0; i < 2; i++) {
        int f = i * 256 + tid;
        *(float4*)(s + f * 4) = *(const float4*)(src + f * 4);
    }
    __syncthreads();
    const int b = tid >> 1;
    const int w0 = (tid & 1) * 4;
    uint32_t o[4];
#pragma unroll
    for (int q = 0; q < 4; q++) {
        int w = w0 + q;
        int j = b * 8 + (w >> 1) + (w & 1) * 4;
        o[q] = f2h2(s[2 * j], s[2 * j + 1]);
    }
    *(uint4*)(XP + (size_t)m * 1024 + tid * 4) = make_uint4(o[0], o[1], o[2], o[3]);
}

__global__ void wprep4_h(const float* __restrict__ W0, const float* __restrict__ W1,
                         const float* __restrict__ W2, const float* __restrict__ W3,
                         uint32_t* __restrict__ P0, uint32_t* __restrict__ P1,
                         uint32_t* __restrict__ P2, uint32_t* __restrict__ P3) {
    __shared__ float s[16 * 260];
    const int n0 = blockIdx.x * 256;
    const int kb = blockIdx.y;
    const int z  = blockIdx.z;
    const int tid = threadIdx.x;
    const float* W = (z == 0) ? W0 : (z == 1) ? W1 : (z == 2) ? W2 : W3;
    uint32_t* WP   = (z == 0) ? P0 : (z == 1) ? P1 : (z == 2) ? P2 : P3;
#pragma unroll
    for (int i = 0; i < 4; i++) {
        int f = i * 256 + tid;
        int r = f >> 6, c4 = (f & 63) * 4;
        float4 v = *(const float4*)(W + (size_t)(kb * 16 + r) * 2048 + n0 + c4);
        *(float4*)(s + r * 260 + c4) = v;
    }
    __syncthreads();
    const int n = tid;
    uint32_t o[8];
#pragma unroll
    for (int w = 0; w < 8; w++) {
        int j = (w >> 1) + (w & 1) * 4;
        o[w] = f2h2(s[(2 * j) * 260 + n], s[(2 * j + 1) * 260 + n]);
    }
    uint32_t* dst = WP + ((size_t)kb * 2048 + n0 + n) * 8;
    *(uint4*)(dst)     = make_uint4(o[0], o[1], o[2], o[3]);
    *(uint4*)(dst + 4) = make_uint4(o[4], o[5], o[6], o[7]);
}

// ---------------------------------------------------------------------------
// PERSISTENT fp16 tensor-core GEMM (R13/R14, verified; 2-stage BK32).
// Grid = 296 CTAs. Tile map: bx = t&15, by = (t>>4)&31, z = t>>9.
// modes: 0 plain fp32 C; 1 Q->QPh (qscale incl. log2e); 2 K->k_out+KPh;
//        3 V->v_out+VPh
// ---------------------------------------------------------------------------
#define HASTR 24
#define HABUF (128 * HASTR)
#define HBBUF (2 * 128 * 8)
#define HGBUF (HABUF + HBBUF)

__global__ __launch_bounds__(256, 2)
void gemm_h(const uint32_t* __restrict__ Ap,
            const uint32_t* __restrict__ Wa, const uint32_t* __restrict__ Wb,
            const uint32_t* __restrict__ Wc,
            const float* __restrict__ ba, const float* __restrict__ bb,
            const float* __restrict__ bc,
            float* __restrict__ ra, float* __restrict__ rb, float* __restrict__ rc,
            uint32_t* __restrict__ pa, uint32_t* __restrict__ pb, uint32_t* __restrict__ pc,
            int modebase, int ntiles)
{
    extern __shared__ uint32_t smu[];

    const int tid  = threadIdx.x;
    const int lane = tid & 31;
    const int wid  = tid >> 5;
    const int mb   = (wid >> 1) * 32;
    const int nb   = (wid & 1) * 64;
    const int lr   = lane >> 2;
    const int lc   = lane & 3;

    for (int tile = blockIdx.x; tile < ntiles; tile += gridDim.x) {
        const int bx = tile & 15;
        const int by = (tile >> 4) & 31;
        const int z  = tile >> 9;
        const uint32_t* WP = (z == 0) ? Wa : (z == 1) ? Wb : Wc;
        const float* bias  = (z == 0) ? ba : (z == 1) ? bb : bc;
        float* Craw        = (z == 0) ? ra : (z == 1) ? rb : rc;
        uint32_t* Cpair    = (z == 0) ? pa : (z == 1) ? pb : pc;
        const int mode = modebase ? (1 + z) : 0;

        float acc[2][8][4];
#pragma unroll
        for (int f = 0; f < 2; f++)
#pragma unroll
            for (int g = 0; g < 8; g++)
#pragma unroll
                for (int t = 0; t < 4; t++) acc[f][g][t] = 0.f;

        auto issue = [&](int kt, int buf) {
            uint32_t* As = smu + buf * HGBUF;
            uint32_t* Bs = As + HABUF;
#pragma unroll
            for (int j = 0; j < 2; j++) {
                int idx = j * 256 + tid;
                int m = idx >> 2, ch = idx & 3;
                cpa16(As + m * HASTR + ch * 4,
                      Ap + (size_t)(by * 128 + m) * 1024 + kt * 16 + ch * 4);
            }
#pragma unroll
            for (int j = 0; j < 2; j++) {
                int idx = j * 256 + tid;
                int kb = idx >> 8, r = idx & 255, n = r >> 1, ch = r & 1;
                cpa16(Bs + kb * 1024 + n * 8 + ch * 4,
                      WP + ((size_t)(kt * 2 + kb) * 2048 + bx * 128 + n) * 8 + ch * 4);
            }
        };

        issue(0, 0);
        CP_COMMIT;

        for (int kt = 0; kt < 64; kt++) {
            CP_WAIT0;
            __syncthreads();
            if (kt < 63) { issue(kt + 1, (kt + 1) & 1); CP_COMMIT; }

            const uint32_t* As = smu + (kt & 1) * HGBUF;
            const uint32_t* Bs = As + HABUF;

#pragma unroll
            for (int kb = 0; kb < 2; kb++) {
                const int ao = kb * 8 + 2 * lc;
                uint2 x0 = *(const uint2*)(As + (mb + lr) * HASTR + ao);
                uint2 x1 = *(const uint2*)(As + (mb + lr + 8) * HASTR + ao);
                uint2 x2 = *(const uint2*)(As + (mb + 16 + lr) * HASTR + ao);
                uint2 x3 = *(const uint2*)(As + (mb + 24 + lr) * HASTR + ao);
                uint32_t a0[4] = {x0.x, x1.x, x0.y, x1.y};
                uint32_t a1[4] = {x2.x, x3.x, x2.y, x3.y};
                const uint32_t* bp = Bs + kb * 1024 + (nb + lr) * 8 + 2 * lc;
#pragma unroll
                for (int g = 0; g < 8; g++) {
                    uint2 bv = *(const uint2*)(bp + g * 64);
                    uint32_t b[2] = {bv.x, bv.y};
                    mma16(acc[0][g], a0, b);
                    mma16(acc[1][g], a1, b);
                }
            }
            __syncthreads();
        }

        // qscale = (1/sqrt(128)) * log2(e): attention scores arrive in the
        // log2 domain so softmax uses bare exp2f (saves the FMUL in __expf).
        const float qscale = 0.08838834764831845f * 1.4426950408889634f;
#pragma unroll
        for (int f = 0; f < 2; f++) {
#pragma unroll
            for (int g = 0; g < 8; g++) {
#pragma unroll
                for (int ii = 0; ii < 2; ii++) {
                    int row = by * 128 + mb + f * 16 + lr + 8 * ii;
                    int col0 = bx * 128 + nb + g * 8 + lc * 2;
                    float v0 = acc[f][g][ii * 2 + 0] + bias[col0];
                    float v1 = acc[f][g][ii * 2 + 1] + bias[col0 + 1];
                    if (mode == 0) {
                        float* p = Craw + (size_t)row * Dd + col0;
                        p[0] = v0; p[1] = v1;
                    } else {
                        int b_ = row >> 11, s_ = row & 2047;
                        int h_ = col0 >> 7, d_ = col0 & 127;
                        size_t bh = (size_t)(b_ * Hh + h_);
                        if (mode >= 2) {
                            float* p = Craw + (bh * Ss + s_) * HD + d_;
                            p[0] = v0; p[1] = v1;
                        }
                        if (mode == 3) {
                            float u0 = __shfl_xor_sync(0xffffffffu, v0, 4);
                            float u1 = __shfl_xor_sync(0xffffffffu, v1, 4);
                            if (!(lr & 1)) {
                                int js = s_ >> 1;
                                size_t slot = (size_t)(js >> 3) * 8 + ppos(js & 7);
                                Cpair[(bh * 128 + d_) * 1024 + slot]     = f2h2(v0, u0);
                                Cpair[(bh * 128 + d_ + 1) * 1024 + slot] = f2h2(v1, u1);
                            }
                        } else {
                            float s0 = (mode == 1) ? v0 * qscale : v0;
                            float s1 = (mode == 1) ? v1 * qscale : v1;
                            int j = d_ >> 1;
                            Cpair[(bh * Ss + s_) * 64 + (j >> 3) * 8 + ppos(j & 7)] = f2h2(s0, s1);
                        }
                    }
                }
            }
        }
    }
}

// ---------------------------------------------------------------------------
// fp16 flash attention (R14 shape, verified at 142.2us): 128-thread CTAs,
// Q-tile 64 (4 warps x 16 rows), 2 CTAs/SM, KV tiles 64 double-buffered.
// Softmax in log2 domain (Q pre-scaled by log2e): bare exp2f.
// ---------------------------------------------------------------------------
#define HQS 72
#define HKS 72
#define HVS 40
#define ASQ (64 * HQS)
#define ASK (64 * HKS)
#define ASV (128 * HVS)

__global__ __launch_bounds__(128, 2)
void attn_h(const uint32_t* __restrict__ QP, const uint32_t* __restrict__ KP,
            const uint32_t* __restrict__ VP, uint32_t* __restrict__ AP)
{
    extern __shared__ uint32_t smu[];
    uint32_t* sQ = smu;
    uint32_t* sK = sQ + ASQ;
    uint32_t* sV = sK + 2 * ASK;

    const int qt  = (gridDim.x - 1) - blockIdx.x;
    const int bh  = blockIdx.y;
    const int tid = threadIdx.x;
    const int lane = tid & 31;
    const int wid  = tid >> 5;
    const int lr   = lane >> 2;
    const int lc   = lane & 3;
    const int m_off = wid * 16;

    const uint32_t* Qg = QP + ((size_t)bh * Ss + (size_t)qt * 64) * 64;
    const uint32_t* Kg = KP + (size_t)bh * Ss * 64;
    const uint32_t* Vg = VP + (size_t)bh * 128 * 1024;

#pragma unroll
    for (int i = 0; i < 8; i++) {
        int idx = i * 128 + tid;
        int row = idx >> 4, ch = idx & 15;
        cpa16(sQ + row * HQS + ch * 4, Qg + (size_t)row * 64 + ch * 4);
    }
    CP_COMMIT;
#pragma unroll
    for (int i = 0; i < 8; i++) {
        int idx = i * 128 + tid;
        int row = idx >> 4, ch = idx & 15;
        cpa16(sK + row * HKS + ch * 4, Kg + (size_t)row * 64 + ch * 4);
    }
#pragma unroll
    for (int i = 0; i < 8; i++) {
        int idx = i * 128 + tid;
        int d = idx >> 3, ch = idx & 7;
        cpa16(sV + d * HVS + ch * 4, Vg + (size_t)d * 1024 + ch * 4);
    }
    CP_COMMIT;

    CP_WAIT1;
    __syncthreads();
    uint32_t qf[8][4];
#pragma unroll
    for (int kb = 0; kb < 8; kb++) {
        uint2 q0 = *(const uint2*)(sQ + (m_off + lr) * HQS + kb * 8 + 2 * lc);
        uint2 q1 = *(const uint2*)(sQ + (m_off + lr + 8) * HQS + kb * 8 + 2 * lc);
        qf[kb][0] = q0.x; qf[kb][1] = q1.x; qf[kb][2] = q0.y; qf[kb][3] = q1.y;
    }

    float o[16][4];
#pragma unroll
    for (int n = 0; n < 16; n++)
#pragma unroll
        for (int j = 0; j < 4; j++) o[n][j] = 0.f;
    float m0 = -1e30f, m1 = -1e30f, l0 = 0.f, l1 = 0.f;

    const int tmax = qt;

    for (int t = 0; t <= tmax; t++) {
        const int buf = t & 1;
        if (t < tmax) {
            const int nb2 = (t + 1) & 1;
            uint32_t* dK = sK + nb2 * ASK;
            uint32_t* dV = sV + nb2 * ASV;
            const uint32_t* gK = Kg + (size_t)(t + 1) * 64 * 64;
            const uint32_t* gV = Vg + (size_t)(t + 1) * 32;
#pragma unroll
            for (int i = 0; i < 8; i++) {
                int idx = i * 128 + tid;
                int row = idx >> 4, ch = idx & 15;
                cpa16(dK + row * HKS + ch * 4, gK + (size_t)row * 64 + ch * 4);
            }
#pragma unroll
            for (int i = 0; i < 8; i++) {
                int idx = i * 128 + tid;
                int d = idx >> 3, ch = idx & 7;
                cpa16(dV + d * HVS + ch * 4, gV + (size_t)d * 1024 + ch * 4);
            }
            CP_COMMIT;
            CP_WAIT1;
        } else {
            CP_WAIT0;
        }
        __syncthreads();

        {
            const uint32_t* sKb = sK + buf * ASK;
            const uint32_t* sVb = sV + buf * ASV;

            // ---- S = Q @ K^T (log2-domain scores) ----
            float c[8][4];
#pragma unroll
            for (int n = 0; n < 8; n++)
#pragma unroll
                for (int j = 0; j < 4; j++) c[n][j] = 0.f;

#pragma unroll
            for (int kb = 0; kb < 8; kb++) {
                const uint32_t* kp = sKb + lr * HKS + kb * 8 + 2 * lc;
#pragma unroll
                for (int nf = 0; nf < 8; nf++) {
                    uint2 kv = *(const uint2*)(kp + nf * 8 * HKS);
                    uint32_t b[2] = {kv.x, kv.y};
                    mma16(c[nf], qf[kb], b);
                }
            }

            // ---- causal mask ----
            if (t * 64 + 63 > qt * 64 + m_off) {
#pragma unroll
                for (int nf = 0; nf < 8; nf++) {
#pragma unroll
                    for (int j = 0; j < 4; j++) {
                        int col = t * 64 + nf * 8 + 2 * lc + (j & 1);
                        int row = qt * 64 + m_off + lr + 8 * (j >> 1);
                        if (col > row) c[nf][j] = -1e30f;
                    }
                }
            }

            // ---- online softmax, base-2 (rows lr, lr+8) ----
            float mt0 = -1e30f, mt1 = -1e30f;
#pragma unroll
            for (int nf = 0; nf < 8; nf++) {
                mt0 = fmaxf(mt0, fmaxf(c[nf][0], c[nf][1]));
                mt1 = fmaxf(mt1, fmaxf(c[nf][2], c[nf][3]));
            }
#pragma unroll
            for (int d = 1; d <= 2; d <<= 1) {
                mt0 = fmaxf(mt0, __shfl_xor_sync(0xffffffffu, mt0, d));
                mt1 = fmaxf(mt1, __shfl_xor_sync(0xffffffffu, mt1, d));
            }
            float nm0 = fmaxf(m0, mt0), nm1 = fmaxf(m1, mt1);
            float corr0 = exp2f(m0 - nm0), corr1 = exp2f(m1 - nm1);
            m0 = nm0; m1 = nm1;

            float s0 = 0.f, s1 = 0.f;
#pragma unroll
            for (int nf = 0; nf < 8; nf++) {
                c[nf][0] = exp2f(c[nf][0] - nm0); s0 += c[nf][0];
                c[nf][1] = exp2f(c[nf][1] - nm0); s0 += c[nf][1];
                c[nf][2] = exp2f(c[nf][2] - nm1); s1 += c[nf][2];
                c[nf][3] = exp2f(c[nf][3] - nm1); s1 += c[nf][3];
            }
#pragma unroll
            for (int d = 1; d <= 2; d <<= 1) {
                s0 += __shfl_xor_sync(0xffffffffu, s0, d);
                s1 += __shfl_xor_sync(0xffffffffu, s1, d);
            }
            l0 = l0 * corr0 + s0;
            l1 = l1 * corr1 + s1;

            if (__any_sync(0xffffffffu, (corr0 != 1.f) || (corr1 != 1.f))) {
#pragma unroll
                for (int n = 0; n < 16; n++) {
                    o[n][0] *= corr0; o[n][1] *= corr0;
                    o[n][2] *= corr1; o[n][3] *= corr1;
                }
            }

            // ---- O += P @ V  (C-frag layout == A-frag layout: no shfl) ----
#pragma unroll
            for (int kp2 = 0; kp2 < 4; kp2++) {
                uint32_t a[4];
                a[0] = f2h2(c[2 * kp2][0],     c[2 * kp2][1]);
                a[1] = f2h2(c[2 * kp2][2],     c[2 * kp2][3]);
                a[2] = f2h2(c[2 * kp2 + 1][0], c[2 * kp2 + 1][1]);
                a[3] = f2h2(c[2 * kp2 + 1][2], c[2 * kp2 + 1][3]);
                const uint32_t* vp = sVb + lr * HVS + kp2 * 8 + 2 * lc;
#pragma unroll
                for (int nf = 0; nf < 16; nf++) {
                    uint2 vv = *(const uint2*)(vp + nf * 8 * HVS);
                    uint32_t b[2] = {vv.x, vv.y};
                    mma16(o[nf], a, b);
                }
            }
        }
        __syncthreads();
    }

    // ---- epilogue: normalize, write APh (pair layout for final GEMM) ----
    const float inv0 = 1.0f / l0;
    const float inv1 = 1.0f / l1;
    const int b = bh / Hh;
    const int h = bh % Hh;
    const size_t mrow0 = (size_t)b * 2048 + qt * 64 + m_off + lr;
    const size_t mrow1 = mrow0 + 8;
#pragma unroll
    for (int nf = 0; nf < 16; nf++) {
        int j = h * 64 + nf * 4 + lc;
        size_t slot = (size_t)(j >> 3) * 8 + ppos(j & 7);
        AP[mrow0 * 1024 + slot] = f2h2(o[nf][0] * inv0, o[nf][1] * inv0);
        AP[mrow1 * 1024 + slot] = f2h2(o[nf][2] * inv1, o[nf][3] * inv1);
    }
}

// ---------------------------------------------------------------------------

extern "C" void kernel_launch(void* const* d_in, const int* in_sizes, int n_in,
                              void* d_out, int out_size)
{
    const float* x  = (const float*)d_in[0];
    const float* Wq = (const float*)d_in[1];
    const float* bq = (const float*)d_in[2];
    const float* Wk = (const float*)d_in[3];
    const float* bk = (const float*)d_in[4];
    const float* Wv = (const float*)d_in[5];
    const float* bv = (const float*)d_in[6];
    const float* Wd = (const float*)d_in[7];
    const float* bd = (const float*)d_in[8];

    float* out = (float*)d_out;
    float* a_out = out;
    float* k_out = out + (size_t)Bb * Ss * Dd;
    float* v_out = k_out + (size_t)Bb * Ss * Dd;

    uint32_t *xp, *wpq, *wpk, *wpv, *wpd, *qp, *kp, *vp, *ap;
    cudaGetSymbolAddress((void**)&xp,  g_XPh);
    cudaGetSymbolAddress((void**)&wpq, g_WPq);
    cudaGetSymbolAddress((void**)&wpk, g_WPk);
    cudaGetSymbolAddress((void**)&wpv, g_WPv);
    cudaGetSymbolAddress((void**)&wpd, g_WPd);
    cudaGetSymbolAddress((void**)&qp,  g_QPh);
    cudaGetSymbolAddress((void**)&kp,  g_KPh);
    cudaGetSymbolAddress((void**)&vp,  g_VPh);
    cudaGetSymbolAddress((void**)&ap,  g_APh);

    xprep_h<<<Mtot, 256>>>(x, xp);
    wprep4_h<<<dim3(8, 128, 4), 256>>>(Wq, Wk, Wv, Wd, wpq, wpk, wpv, wpd);

    size_t gsm = 2 * (size_t)HGBUF * sizeof(uint32_t);
    cudaFuncSetAttribute(gemm_h, cudaFuncAttributeMaxDynamicSharedMemorySize, (int)gsm);

    const int PERSIST = 296;   // 2 CTAs/SM x 148 SMs

    // fused QKV (persistent): tiles 0..1535, z = tile>>9; modes 1,2,3
    gemm_h<<<PERSIST, 256, gsm>>>(
        xp, wpq, wpk, wpv, bq, bk, bv,
        nullptr, k_out, v_out, qp, kp, vp, 1, 1536);

    size_t asm_ = (size_t)(ASQ + 2 * ASK + 2 * ASV) * sizeof(uint32_t);
    cudaFuncSetAttribute(attn_h, cudaFuncAttributeMaxDynamicSharedMemorySize, (int)asm_);
    attn_h<<<dim3(Ss / 64, Bb * Hh), 128, asm_>>>(qp, kp, vp, ap);

    // final projection (persistent): tiles 0..511, mode 0
    gemm_h<<<PERSIST, 256, gsm>>>(
        ap, wpd, wpd, wpd, bd, bd, bd,
        a_out, a_out, a_out, nullptr, nullptr, nullptr, 0, 512);
}